// round 13
// baseline (speedup 1.0000x reference)
#include <cuda_runtime.h>
#include <cuda_bf16.h>
#include <math_constants.h>
#include <cstdint>

#define BATCH 4
#define LSEQ  1024
#define NH    6
#define DHEAD 128
#define BHN   (BATCH*NH)
#define SJ    136   // smem row stride (bf16) for 128-elem rows; 272B = 17x16B, conflict-free

#define CO_ELEMS  ((size_t)BHN*LSEQ*LSEQ)          // 25165824
#define W_ELEMS   ((size_t)BATCH*LSEQ)             // 4096
// Vh follows w in the output buffer.

// ---------------- device scratch (static; no dynamic allocation) --------------
__device__ int    g_valid[BATCH*LSEQ];
__device__ double g_sum[NH], g_sumsq[NH];
__device__ float  g_alpha[NH], g_beta[NH];
__device__ float  g_w[BHN*LSEQ];
__device__ float  g_a2[NH], g_b2[NH];

// =================== K0: mask dtype detection + init =====================
// bool masks arrive as u8/bf16/i32/f32. Row 0 of batch 0 of pad_mask is >=512
// consecutive Trues -> first 512 32-bit words carry an unambiguous signature.
__global__ void k0_setup(const unsigned int* __restrict__ padw,
                         const unsigned char* __restrict__ bx) {
    __shared__ int flag1, flag2;
    int tid = threadIdx.x;
    if (tid == 0) { flag1 = 0; flag2 = 0; }
    for (int i = tid; i < BHN*LSEQ; i += blockDim.x) g_w[i] = 0.f;
    if (tid < NH) { g_sum[tid] = 0.0; g_sumsq[tid] = 0.0; }
    __syncthreads();
    for (int i = tid; i < 512; i += blockDim.x) {
        unsigned int v = padw[i];
        if (v == 0x01010101u) atomicOr(&flag1, 1);
        if (v == 0x3F803F80u) atomicOr(&flag2, 1);
    }
    __syncthreads();
    int width = flag1 ? 1 : (flag2 ? 2 : 4);
    const unsigned short* b16 = (const unsigned short*)bx;
    const unsigned int*   b32 = (const unsigned int*)bx;
    for (int x = tid; x < BATCH*LSEQ; x += blockDim.x) {
        int v;
        if (width == 1)      v = (bx[x] == 0);
        else if (width == 2) v = (b16[x] == 0);
        else                 v = (b32[x] == 0);
        g_valid[x] = v;   // 1 = valid (not padded)
    }
}

// =================== K1b: Vh = split_heads(V) into output tail ===========
__global__ void k1_vh(const float* __restrict__ V, float* __restrict__ Vh) {
    int bl = blockIdx.x;
    int b = bl >> 10, l = bl & 1023;
    int t = threadIdx.x;               // 0..191 float4
    int h = (t*4) >> 7;
    int d = (t*4) & 127;
    float4 v = *(const float4*)(V + ((size_t)bl)*768 + t*4);
    *(float4*)(Vh + (((size_t)(b*NH + h))*LSEQ + l)*DHEAD + d) = v;
}

// =================== K2: scores GEMM (bf16 hi/lo split) + BN1 stats ======
// Tile 64x128 per CTA (105KB smem -> 2 CTAs/SM, 4 warps/SMSP).
// 8 warps in 2x4; warp tile 32x32; acc = 32 regs; launch_bounds caps regs 128.
// q2/k2 computed in-register during the tile load (k1_norms kernel deleted).
// scores = -(q2_i + k2_j - 2*qk); qk = qh*kh + qh*kl + ql*kh.
__global__ void __launch_bounds__(256, 2) k2_scores(const float* __restrict__ Q,
                                                    const float* __restrict__ K,
                                                    float* __restrict__ co) {
    extern __shared__ __nv_bfloat16 sm[];
    __nv_bfloat16* qh = sm;                 // 64 x SJ
    __nv_bfloat16* ql = qh + 64*SJ;
    __nv_bfloat16* kh = ql + 64*SJ;         // 128 x SJ
    __nv_bfloat16* kl = kh + 128*SJ;
    float* sQ2 = (float*)(kl + 128*SJ);     // 64
    float* sK2 = sQ2 + 64;                  // 128
    __shared__ float rs[8], rq[8];

    int tid = threadIdx.x;
    int w = tid >> 5, lane = tid & 31;
    int jt = blockIdx.x, it = blockIdx.y, bh = blockIdx.z;
    int b = bh / NH, h = bh % NH;

    const float* Qg = Q + ((size_t)(b*LSEQ + it*64))*768 + h*DHEAD;
    const float* Kg = K + ((size_t)(b*LSEQ + jt*128))*768 + h*DHEAD;

    // ---- load Q tile (64 rows): one row per warp per iter; fuse q2 ----
    #pragma unroll
    for (int p = 0; p < 2; ++p) {
        int r = w + 8*p;                   // rows 0..15 ... wait: 8 warps x 8 iters
        (void)r;
    }
    #pragma unroll
    for (int p = 0; p < 8; ++p) {
        int r = 8*p + w;                   // 0..63
        float4 v = *(const float4*)(Qg + r*768 + lane*4);
        __nv_bfloat16 hx = __float2bfloat16(v.x), hy = __float2bfloat16(v.y),
                      hz = __float2bfloat16(v.z), hw = __float2bfloat16(v.w);
        __nv_bfloat162* dh = (__nv_bfloat162*)(qh + r*SJ + lane*4);
        __nv_bfloat162* dl = (__nv_bfloat162*)(ql + r*SJ + lane*4);
        __nv_bfloat162 h0; h0.x = hx; h0.y = hy;
        __nv_bfloat162 h1; h1.x = hz; h1.y = hw;
        dh[0] = h0; dh[1] = h1;
        __nv_bfloat162 l0, l1;
        l0.x = __float2bfloat16(v.x - __bfloat162float(hx));
        l0.y = __float2bfloat16(v.y - __bfloat162float(hy));
        l1.x = __float2bfloat16(v.z - __bfloat162float(hz));
        l1.y = __float2bfloat16(v.w - __bfloat162float(hw));
        dl[0] = l0; dl[1] = l1;
        float s = v.x*v.x + v.y*v.y + v.z*v.z + v.w*v.w;
        #pragma unroll
        for (int o = 16; o; o >>= 1) s += __shfl_xor_sync(0xffffffffu, s, o);
        if (!lane) sQ2[r] = s;
    }
    // ---- load K tile (128 rows): fuse k2 ----
    #pragma unroll
    for (int p = 0; p < 16; ++p) {
        int r = 8*p + w;                   // 0..127
        float4 v = *(const float4*)(Kg + r*768 + lane*4);
        __nv_bfloat16 hx = __float2bfloat16(v.x), hy = __float2bfloat16(v.y),
                      hz = __float2bfloat16(v.z), hw = __float2bfloat16(v.w);
        __nv_bfloat162* dh = (__nv_bfloat162*)(kh + r*SJ + lane*4);
        __nv_bfloat162* dl = (__nv_bfloat162*)(kl + r*SJ + lane*4);
        __nv_bfloat162 h0; h0.x = hx; h0.y = hy;
        __nv_bfloat162 h1; h1.x = hz; h1.y = hw;
        dh[0] = h0; dh[1] = h1;
        __nv_bfloat162 l0, l1;
        l0.x = __float2bfloat16(v.x - __bfloat162float(hx));
        l0.y = __float2bfloat16(v.y - __bfloat162float(hy));
        l1.x = __float2bfloat16(v.z - __bfloat162float(hz));
        l1.y = __float2bfloat16(v.w - __bfloat162float(hw));
        dl[0] = l0; dl[1] = l1;
        float s = v.x*v.x + v.y*v.y + v.z*v.z + v.w*v.w;
        #pragma unroll
        for (int o = 16; o; o >>= 1) s += __shfl_xor_sync(0xffffffffu, s, o);
        if (!lane) sK2[r] = s;
    }
    __syncthreads();

    int wm = w >> 2, wn = w & 3;           // 2x4 warps; warp tile 32x32
    float acc[2][4][4];
    #pragma unroll
    for (int mi = 0; mi < 2; ++mi)
        #pragma unroll
        for (int ni = 0; ni < 4; ++ni)
            #pragma unroll
            for (int r = 0; r < 4; ++r) acc[mi][ni][r] = 0.f;

    const __nv_bfloat16* Asrc[3] = {qh, qh, ql};
    const __nv_bfloat16* Bsrc[3] = {kh, kl, kh};
    int arow  = wm*32 + (lane & 15);
    int acolo = ((lane >> 4) << 3);
    int bn0   = wn*32 + (lane >> 2);
    int bk    = 2*(lane & 3);

    #pragma unroll
    for (int seg = 0; seg < 3; ++seg) {
        const __nv_bfloat16* A  = Asrc[seg];
        const __nv_bfloat16* Bm = Bsrc[seg];
        #pragma unroll
        for (int kk = 0; kk < 8; ++kk) {
            int k0 = kk*16;
            uint32_t af[2][4];
            #pragma unroll
            for (int mi = 0; mi < 2; ++mi) {
                uint32_t addr = (uint32_t)__cvta_generic_to_shared(
                    A + (arow + mi*16)*SJ + k0 + acolo);
                asm volatile("ldmatrix.sync.aligned.m8n8.x4.shared.b16 {%0,%1,%2,%3}, [%4];"
                    : "=r"(af[mi][0]), "=r"(af[mi][1]), "=r"(af[mi][2]), "=r"(af[mi][3])
                    : "r"(addr));
            }
            #pragma unroll
            for (int ni = 0; ni < 4; ++ni) {
                const __nv_bfloat16* bp0 = Bm + (bn0 + ni*8)*SJ + k0 + bk;
                uint32_t b0 = *(const uint32_t*)bp0;
                uint32_t b1 = *(const uint32_t*)(bp0 + 8);
                #pragma unroll
                for (int mi = 0; mi < 2; ++mi) {
                    asm volatile(
                        "mma.sync.aligned.m16n8k16.row.col.f32.bf16.bf16.f32 "
                        "{%0,%1,%2,%3}, {%4,%5,%6,%7}, {%8,%9}, {%0,%1,%2,%3};"
                        : "+f"(acc[mi][ni][0]), "+f"(acc[mi][ni][1]),
                          "+f"(acc[mi][ni][2]), "+f"(acc[mi][ni][3])
                        : "r"(af[mi][0]), "r"(af[mi][1]), "r"(af[mi][2]), "r"(af[mi][3]),
                          "r"(b0), "r"(b1));
                }
            }
        }
    }

    // epilogue: write raw scores + fp32 partial BN1 stats
    float lsum = 0.f, lsq = 0.f;
    size_t obase = ((size_t)bh*LSEQ + (size_t)it*64)*LSEQ + (size_t)jt*128;
    #pragma unroll
    for (int mi = 0; mi < 2; ++mi) {
        #pragma unroll
        for (int ni = 0; ni < 4; ++ni) {
            int r0 = wm*32 + mi*16 + (lane >> 2);
            int c0 = wn*32 + ni*8  + 2*(lane & 3);
            #pragma unroll
            for (int hf = 0; hf < 2; ++hf) {
                int r = r0 + hf*8;
                float q2v = sQ2[r];
                float s0 = 2.f*acc[mi][ni][hf*2+0] - q2v - sK2[c0];
                float s1 = 2.f*acc[mi][ni][hf*2+1] - q2v - sK2[c0+1];
                *(float2*)(co + obase + (size_t)r*LSEQ + c0) = make_float2(s0, s1);
                lsum += s0 + s1;
                lsq  += s0*s0 + s1*s1;
            }
        }
    }
    #pragma unroll
    for (int o = 16; o; o >>= 1) {
        lsum += __shfl_xor_sync(0xffffffffu, lsum, o);
        lsq  += __shfl_xor_sync(0xffffffffu, lsq,  o);
    }
    if (!lane) { rs[w] = lsum; rq[w] = lsq; }
    __syncthreads();
    if (tid == 0) {
        float S = 0.f, SQ = 0.f;
        #pragma unroll
        for (int i = 0; i < 8; ++i) { S += rs[i]; SQ += rq[i]; }
        atomicAdd(&g_sum[h],   (double)S);
        atomicAdd(&g_sumsq[h], (double)SQ);
    }
}

// =================== K3: fold BN1 into alpha/beta ========================
__global__ void k3_bn1(const float* __restrict__ g1, const float* __restrict__ b1) {
    int h = threadIdx.x;
    if (h < NH) {
        double n   = (double)BATCH * LSEQ * LSEQ;
        double m   = g_sum[h] / n;
        double var = g_sumsq[h] / n - m*m;
        double inv = rsqrt(var + 1e-5);
        float  a   = (float)(inv * (double)g1[h]);
        g_alpha[h] = a;
        g_beta[h]  = b1[h] - (float)m * a;
    }
}

// =================== K4: in-place BN1 + mask(->0) + row softmax ==========
// Fused column-sum epilogue (stripe in smem, one atomic per column per block).
__global__ void __launch_bounds__(512) k4_softmax(float* __restrict__ co) {
    extern __shared__ float dyn[];
    float* stripe = dyn;                                  // [16][1024]
    unsigned char* sval = (unsigned char*)(dyn + 16*1024);// [1024]
    int tid = threadIdx.x, w = tid >> 5, lane = tid & 31;
    int rowblk = blockIdx.x;               // 64 blocks of 16 rows per bh
    int bh = rowblk >> 6;
    int i0 = (rowblk & 63) * 16;
    int b = bh / NH, h = bh % NH;
    for (int x = tid; x < LSEQ; x += 512) sval[x] = (unsigned char)g_valid[b*LSEQ + x];
    __syncthreads();

    int i = i0 + w;
    bool vi = (g_valid[b*LSEQ + i] != 0);
    float alpha = g_alpha[h], beta = g_beta[h];
    float4* p = (float4*)(co + (((size_t)bh)*LSEQ + i)*LSEQ);

    float4 vb[8];
    float mx = -CUDART_INF_F;
    #pragma unroll
    for (int f = 0; f < 8; ++f) {
        int fi = lane + 32*f;
        float4 v = p[fi];
        int j = fi*4;
        float y0 = (vi && sval[j+0]) ? (alpha*v.x + beta) : 0.f;
        float y1 = (vi && sval[j+1]) ? (alpha*v.y + beta) : 0.f;
        float y2 = (vi && sval[j+2]) ? (alpha*v.z + beta) : 0.f;
        float y3 = (vi && sval[j+3]) ? (alpha*v.w + beta) : 0.f;
        vb[f] = make_float4(y0, y1, y2, y3);
        mx = fmaxf(mx, fmaxf(fmaxf(y0, y1), fmaxf(y2, y3)));
    }
    #pragma unroll
    for (int o = 16; o; o >>= 1) mx = fmaxf(mx, __shfl_xor_sync(0xffffffffu, mx, o));
    float sum = 0.f;
    #pragma unroll
    for (int f = 0; f < 8; ++f) {
        float e0 = __expf(vb[f].x - mx);
        float e1 = __expf(vb[f].y - mx);
        float e2 = __expf(vb[f].z - mx);
        float e3 = __expf(vb[f].w - mx);
        vb[f] = make_float4(e0, e1, e2, e3);
        sum += (e0 + e1) + (e2 + e3);
    }
    #pragma unroll
    for (int o = 16; o; o >>= 1) sum += __shfl_xor_sync(0xffffffffu, sum, o);
    float inv = 1.f / sum;
    #pragma unroll
    for (int f = 0; f < 8; ++f) {
        int fi = lane + 32*f;
        float4 out = make_float4(vb[f].x*inv, vb[f].y*inv, vb[f].z*inv, vb[f].w*inv);
        p[fi] = out;
        *(float4*)(stripe + w*1024 + fi*4) = out;
    }
    __syncthreads();
    #pragma unroll
    for (int x = tid; x < 1024; x += 512) {
        float s = 0.f;
        #pragma unroll
        for (int r = 0; r < 16; ++r) s += stripe[r*1024 + x];
        atomicAdd(&g_w[bh*LSEQ + x], s);
    }
}

// =================== K6: BN2 stats -> a2/b2 ==============================
__global__ void k6_bn2(const float* __restrict__ g2, const float* __restrict__ b2) {
    __shared__ double ss[256], sq[256];
    int t = threadIdx.x;
    for (int h = 0; h < NH; ++h) {
        double s = 0.0, q = 0.0;
        for (int x = t; x < BATCH*LSEQ; x += 256) {
            float v = g_w[((x >> 10)*NH + h)*LSEQ + (x & 1023)];
            s += v; q += (double)v * v;
        }
        ss[t] = s; sq[t] = q;
        __syncthreads();
        for (int o = 128; o; o >>= 1) {
            if (t < o) { ss[t] += ss[t+o]; sq[t] += sq[t+o]; }
            __syncthreads();
        }
        if (t == 0) {
            double n   = (double)BATCH * LSEQ;
            double m   = ss[0] / n;
            double var = sq[0] / n - m*m;
            double inv = rsqrt(var + 1e-5);
            float  a   = (float)(inv * (double)g2[h]);
            g_a2[h] = a;
            g_b2[h] = b2[h] - (float)m * a;
        }
        __syncthreads();
    }
}

// =================== K7: gate + length-masked softmax over L =============
__global__ void __launch_bounds__(1024) k7_gate(const float* __restrict__ Wp,
                                                const float* __restrict__ bp,
                                                float* __restrict__ w_out) {
    __shared__ float red[1024];
    int b = blockIdx.x, l = threadIdx.x;
    float z = bp[0] - bp[1];
    #pragma unroll
    for (int h = 0; h < NH; ++h) {
        float wv = g_a2[h]*g_w[(b*NH + h)*LSEQ + l] + g_b2[h];
        z += (Wp[h] - Wp[NH + h]) * wv;
    }
    float p0 = 1.f / (1.f + __expf(-z));
    bool valid = (g_valid[b*LSEQ + l] != 0);
    float val = valid ? p0 : -CUDART_INF_F;

    red[l] = val;
    __syncthreads();
    for (int o = 512; o; o >>= 1) {
        if (l < o) red[l] = fmaxf(red[l], red[l+o]);
        __syncthreads();
    }
    float mx = red[0];
    __syncthreads();
    float e = valid ? __expf(val - mx) : 0.f;
    red[l] = e;
    __syncthreads();
    for (int o = 512; o; o >>= 1) {
        if (l < o) red[l] += red[l+o];
        __syncthreads();
    }
    w_out[b*LSEQ + l] = e / red[0];
}

// ============================= launcher ==================================
extern "C" void kernel_launch(void* const* d_in, const int* in_sizes, int n_in,
                              void* d_out, int out_size) {
    const float* Q   = (const float*)d_in[0];
    const float* K   = (const float*)d_in[1];
    const float* V   = (const float*)d_in[2];
    const void*  pad = d_in[3];
    const void*  bx  = d_in[4];
    const float* g1  = (const float*)d_in[5];
    const float* b1  = (const float*)d_in[6];
    const float* g2  = (const float*)d_in[7];
    const float* b2  = (const float*)d_in[8];
    const float* Wp  = (const float*)d_in[9];
    const float* bp  = (const float*)d_in[10];

    float* co    = (float*)d_out;                  // (B,H,L,L)
    float* w_out = co + CO_ELEMS;                  // (B,L,1)
    float* vh    = w_out + W_ELEMS;                // (B,H,L,DH)

    static int smem_set = 0;
    const int K2_SMEM = (2*64 + 2*128)*SJ*2 + (64+128)*4;  // 105216 B
    const int K4_SMEM = 16*1024*4 + 1024;                  // 66560 B
    if (!smem_set) {
        cudaFuncSetAttribute(k2_scores, cudaFuncAttributeMaxDynamicSharedMemorySize, K2_SMEM);
        cudaFuncSetAttribute(k4_softmax, cudaFuncAttributeMaxDynamicSharedMemorySize, K4_SMEM);
        smem_set = 1;
    }

    k0_setup<<<1, 256>>>((const unsigned int*)pad, (const unsigned char*)bx);
    k1_vh<<<BATCH*LSEQ, 192>>>(V, vh);
    k2_scores<<<dim3(8, 16, BHN), 256, K2_SMEM>>>(Q, K, co);
    k3_bn1<<<1, 32>>>(g1, b1);
    k4_softmax<<<BHN*64, 512, K4_SMEM>>>(co);
    k6_bn2<<<1, 256>>>(g2, b2);
    k7_gate<<<BATCH, 1024>>>(Wp, bp, w_out);
}

// round 14
// speedup vs baseline: 1.1148x; 1.1148x over previous
#include <cuda_runtime.h>
#include <cuda_bf16.h>
#include <math_constants.h>
#include <cstdint>

#define BATCH 4
#define LSEQ  1024
#define NH    6
#define DHEAD 128
#define BHN   (BATCH*NH)
#define SJ    136   // smem row stride (bf16) for 128-elem rows; conflict-free

#define CO_ELEMS  ((size_t)BHN*LSEQ*LSEQ)          // 25165824
#define W_ELEMS   ((size_t)BATCH*LSEQ)             // 4096
// Vh follows w in the output buffer.

// ---------------- device scratch (static; no dynamic allocation) --------------
__device__ int    g_valid[BATCH*LSEQ];
__device__ double g_sum[NH], g_sumsq[NH];
__device__ float  g_alpha[NH], g_beta[NH];
__device__ float  g_w[BHN*LSEQ];
__device__ float  g_a2[NH], g_b2[NH];

// =================== K0: mask dtype detection + init =====================
// bool masks arrive as u8/bf16/i32/f32. Row 0 of batch 0 of pad_mask is >=512
// consecutive Trues -> first 512 32-bit words carry an unambiguous signature.
__global__ void k0_setup(const unsigned int* __restrict__ padw,
                         const unsigned char* __restrict__ bx) {
    __shared__ int flag1, flag2;
    int tid = threadIdx.x;
    if (tid == 0) { flag1 = 0; flag2 = 0; }
    for (int i = tid; i < BHN*LSEQ; i += blockDim.x) g_w[i] = 0.f;
    if (tid < NH) { g_sum[tid] = 0.0; g_sumsq[tid] = 0.0; }
    __syncthreads();
    for (int i = tid; i < 512; i += blockDim.x) {
        unsigned int v = padw[i];
        if (v == 0x01010101u) atomicOr(&flag1, 1);
        if (v == 0x3F803F80u) atomicOr(&flag2, 1);
    }
    __syncthreads();
    int width = flag1 ? 1 : (flag2 ? 2 : 4);
    const unsigned short* b16 = (const unsigned short*)bx;
    const unsigned int*   b32 = (const unsigned int*)bx;
    for (int x = tid; x < BATCH*LSEQ; x += blockDim.x) {
        int v;
        if (width == 1)      v = (bx[x] == 0);
        else if (width == 2) v = (b16[x] == 0);
        else                 v = (b32[x] == 0);
        g_valid[x] = v;   // 1 = valid (not padded)
    }
}

// =================== K1b: Vh = split_heads(V) into output tail ===========
__global__ void k1_vh(const float* __restrict__ V, float* __restrict__ Vh) {
    int bl = blockIdx.x;
    int b = bl >> 10, l = bl & 1023;
    int t = threadIdx.x;               // 0..191 float4
    int h = (t*4) >> 7;
    int d = (t*4) & 127;
    float4 v = *(const float4*)(V + ((size_t)bl)*768 + t*4);
    *(float4*)(Vh + (((size_t)(b*NH + h))*LSEQ + l)*DHEAD + d) = v;
}

// =================== K2: scores GEMM (bf16 hi/lo split) + BN1 stats ======
// R4-proven config: 128x128 tile, 256 threads, 2x4 warps (warp tile 64x32).
// q2/k2 fused into the tile load: row r = w + 8p is loaded entirely by warp w
// (f = tid + 256p => r = f>>5 = w + 8p, col = lane), so a shfl reduction
// during the load produces the squared norms (k1_norms kernel deleted).
// scores = -(q2_i + k2_j - 2*qk); qk = qh*kh + qh*kl + ql*kh (~fp32 accurate).
__global__ void __launch_bounds__(256) k2_scores(const float* __restrict__ Q,
                                                 const float* __restrict__ K,
                                                 float* __restrict__ co) {
    extern __shared__ __nv_bfloat16 sm[];
    __nv_bfloat16* qh = sm;
    __nv_bfloat16* ql = qh + 128*SJ;
    __nv_bfloat16* kh = ql + 128*SJ;
    __nv_bfloat16* kl = kh + 128*SJ;
    float* sQ2 = (float*)(kl + 128*SJ);
    float* sK2 = sQ2 + 128;
    __shared__ float rs[8], rq[8];

    int tid = threadIdx.x;
    int w = tid >> 5, lane = tid & 31;
    int jt = blockIdx.x, it = blockIdx.y, bh = blockIdx.z;
    int b = bh / NH, h = bh % NH;

    const float* Qg = Q + ((size_t)(b*LSEQ + it*128))*768 + h*DHEAD;
    const float* Kg = K + ((size_t)(b*LSEQ + jt*128))*768 + h*DHEAD;
    #pragma unroll
    for (int src = 0; src < 2; ++src) {
        const float* G = src ? Kg : Qg;
        __nv_bfloat16* Dh = src ? kh : qh;
        __nv_bfloat16* Dl = src ? kl : ql;
        float* Sn = src ? sK2 : sQ2;
        #pragma unroll
        for (int p = 0; p < 16; ++p) {
            int r = w + 8*p;                   // row handled by this warp
            float4 v = *(const float4*)(G + r*768 + lane*4);
            __nv_bfloat16 hx = __float2bfloat16(v.x), hy = __float2bfloat16(v.y),
                          hz = __float2bfloat16(v.z), hw = __float2bfloat16(v.w);
            __nv_bfloat162* dh = (__nv_bfloat162*)(Dh + r*SJ + lane*4);
            __nv_bfloat162* dl = (__nv_bfloat162*)(Dl + r*SJ + lane*4);
            __nv_bfloat162 h0; h0.x = hx; h0.y = hy;
            __nv_bfloat162 h1; h1.x = hz; h1.y = hw;
            dh[0] = h0; dh[1] = h1;
            __nv_bfloat162 l0, l1;
            l0.x = __float2bfloat16(v.x - __bfloat162float(hx));
            l0.y = __float2bfloat16(v.y - __bfloat162float(hy));
            l1.x = __float2bfloat16(v.z - __bfloat162float(hz));
            l1.y = __float2bfloat16(v.w - __bfloat162float(hw));
            dl[0] = l0; dl[1] = l1;
            float s = v.x*v.x + v.y*v.y + v.z*v.z + v.w*v.w;
            #pragma unroll
            for (int o = 16; o; o >>= 1) s += __shfl_xor_sync(0xffffffffu, s, o);
            if (!lane) Sn[r] = s;
        }
    }
    __syncthreads();

    int wm = w >> 2, wn = w & 3;                   // 2x4 warps, 64x32 tiles
    float acc[4][4][4];
    #pragma unroll
    for (int mi = 0; mi < 4; ++mi)
        #pragma unroll
        for (int ni = 0; ni < 4; ++ni)
            #pragma unroll
            for (int r = 0; r < 4; ++r) acc[mi][ni][r] = 0.f;

    const __nv_bfloat16* Asrc[3] = {qh, qh, ql};
    const __nv_bfloat16* Bsrc[3] = {kh, kl, kh};
    int arow  = wm*64 + (lane & 15);
    int acolo = ((lane >> 4) << 3);
    int bn0   = wn*32 + (lane >> 2);
    int bk    = 2*(lane & 3);

    #pragma unroll
    for (int seg = 0; seg < 3; ++seg) {
        const __nv_bfloat16* A  = Asrc[seg];
        const __nv_bfloat16* Bm = Bsrc[seg];
        #pragma unroll
        for (int kk = 0; kk < 8; ++kk) {
            int k0 = kk*16;
            uint32_t af[4][4];
            #pragma unroll
            for (int mi = 0; mi < 4; ++mi) {
                uint32_t addr = (uint32_t)__cvta_generic_to_shared(
                    A + (arow + mi*16)*SJ + k0 + acolo);
                asm volatile("ldmatrix.sync.aligned.m8n8.x4.shared.b16 {%0,%1,%2,%3}, [%4];"
                    : "=r"(af[mi][0]), "=r"(af[mi][1]), "=r"(af[mi][2]), "=r"(af[mi][3])
                    : "r"(addr));
            }
            #pragma unroll
            for (int ni = 0; ni < 4; ++ni) {
                const __nv_bfloat16* bp0 = Bm + (bn0 + ni*8)*SJ + k0 + bk;
                uint32_t b0 = *(const uint32_t*)bp0;
                uint32_t b1 = *(const uint32_t*)(bp0 + 8);
                #pragma unroll
                for (int mi = 0; mi < 4; ++mi) {
                    asm volatile(
                        "mma.sync.aligned.m16n8k16.row.col.f32.bf16.bf16.f32 "
                        "{%0,%1,%2,%3}, {%4,%5,%6,%7}, {%8,%9}, {%0,%1,%2,%3};"
                        : "+f"(acc[mi][ni][0]), "+f"(acc[mi][ni][1]),
                          "+f"(acc[mi][ni][2]), "+f"(acc[mi][ni][3])
                        : "r"(af[mi][0]), "r"(af[mi][1]), "r"(af[mi][2]), "r"(af[mi][3]),
                          "r"(b0), "r"(b1));
                }
            }
        }
    }

    // epilogue: write raw scores + fp32 partial BN1 stats
    float lsum = 0.f, lsq = 0.f;
    size_t obase = ((size_t)bh*LSEQ + (size_t)it*128)*LSEQ + (size_t)jt*128;
    #pragma unroll
    for (int mi = 0; mi < 4; ++mi) {
        #pragma unroll
        for (int ni = 0; ni < 4; ++ni) {
            int r0 = wm*64 + mi*16 + (lane >> 2);
            int c0 = wn*32 + ni*8  + 2*(lane & 3);
            #pragma unroll
            for (int hf = 0; hf < 2; ++hf) {
                int r = r0 + hf*8;
                float q2v = sQ2[r];
                float s0 = 2.f*acc[mi][ni][hf*2+0] - q2v - sK2[c0];
                float s1 = 2.f*acc[mi][ni][hf*2+1] - q2v - sK2[c0+1];
                *(float2*)(co + obase + (size_t)r*LSEQ + c0) = make_float2(s0, s1);
                lsum += s0 + s1;
                lsq  += s0*s0 + s1*s1;
            }
        }
    }
    #pragma unroll
    for (int o = 16; o; o >>= 1) {
        lsum += __shfl_xor_sync(0xffffffffu, lsum, o);
        lsq  += __shfl_xor_sync(0xffffffffu, lsq,  o);
    }
    if (!lane) { rs[w] = lsum; rq[w] = lsq; }
    __syncthreads();
    if (tid == 0) {
        float S = 0.f, SQ = 0.f;
        #pragma unroll
        for (int i = 0; i < 8; ++i) { S += rs[i]; SQ += rq[i]; }
        atomicAdd(&g_sum[h],   (double)S);
        atomicAdd(&g_sumsq[h], (double)SQ);
    }
}

// =================== K3: fold BN1 into alpha/beta ========================
__global__ void k3_bn1(const float* __restrict__ g1, const float* __restrict__ b1) {
    int h = threadIdx.x;
    if (h < NH) {
        double n   = (double)BATCH * LSEQ * LSEQ;
        double m   = g_sum[h] / n;
        double var = g_sumsq[h] / n - m*m;
        double inv = rsqrt(var + 1e-5);
        float  a   = (float)(inv * (double)g1[h]);
        g_alpha[h] = a;
        g_beta[h]  = b1[h] - (float)m * a;
    }
}

// =================== K4: in-place BN1 + mask(->0) + row softmax ==========
// Fused column-sum epilogue (stripe in smem, one atomic per column per block).
__global__ void __launch_bounds__(512) k4_softmax(float* __restrict__ co) {
    extern __shared__ float dyn[];
    float* stripe = dyn;                                  // [16][1024]
    unsigned char* sval = (unsigned char*)(dyn + 16*1024);// [1024]
    int tid = threadIdx.x, w = tid >> 5, lane = tid & 31;
    int rowblk = blockIdx.x;               // 64 blocks of 16 rows per bh
    int bh = rowblk >> 6;
    int i0 = (rowblk & 63) * 16;
    int b = bh / NH, h = bh % NH;
    for (int x = tid; x < LSEQ; x += 512) sval[x] = (unsigned char)g_valid[b*LSEQ + x];
    __syncthreads();

    int i = i0 + w;
    bool vi = (g_valid[b*LSEQ + i] != 0);
    float alpha = g_alpha[h], beta = g_beta[h];
    float4* p = (float4*)(co + (((size_t)bh)*LSEQ + i)*LSEQ);

    float4 vb[8];
    float mx = -CUDART_INF_F;
    #pragma unroll
    for (int f = 0; f < 8; ++f) {
        int fi = lane + 32*f;
        float4 v = p[fi];
        int j = fi*4;
        float y0 = (vi && sval[j+0]) ? (alpha*v.x + beta) : 0.f;
        float y1 = (vi && sval[j+1]) ? (alpha*v.y + beta) : 0.f;
        float y2 = (vi && sval[j+2]) ? (alpha*v.z + beta) : 0.f;
        float y3 = (vi && sval[j+3]) ? (alpha*v.w + beta) : 0.f;
        vb[f] = make_float4(y0, y1, y2, y3);
        mx = fmaxf(mx, fmaxf(fmaxf(y0, y1), fmaxf(y2, y3)));
    }
    #pragma unroll
    for (int o = 16; o; o >>= 1) mx = fmaxf(mx, __shfl_xor_sync(0xffffffffu, mx, o));
    float sum = 0.f;
    #pragma unroll
    for (int f = 0; f < 8; ++f) {
        float e0 = __expf(vb[f].x - mx);
        float e1 = __expf(vb[f].y - mx);
        float e2 = __expf(vb[f].z - mx);
        float e3 = __expf(vb[f].w - mx);
        vb[f] = make_float4(e0, e1, e2, e3);
        sum += (e0 + e1) + (e2 + e3);
    }
    #pragma unroll
    for (int o = 16; o; o >>= 1) sum += __shfl_xor_sync(0xffffffffu, sum, o);
    float inv = 1.f / sum;
    #pragma unroll
    for (int f = 0; f < 8; ++f) {
        int fi = lane + 32*f;
        float4 out = make_float4(vb[f].x*inv, vb[f].y*inv, vb[f].z*inv, vb[f].w*inv);
        p[fi] = out;
        *(float4*)(stripe + w*1024 + fi*4) = out;
    }
    __syncthreads();
    #pragma unroll
    for (int x = tid; x < 1024; x += 512) {
        float s = 0.f;
        #pragma unroll
        for (int r = 0; r < 16; ++r) s += stripe[r*1024 + x];
        atomicAdd(&g_w[bh*LSEQ + x], s);
    }
}

// =================== K6: BN2 stats -> a2/b2 ==============================
__global__ void k6_bn2(const float* __restrict__ g2, const float* __restrict__ b2) {
    __shared__ double ss[256], sq[256];
    int t = threadIdx.x;
    for (int h = 0; h < NH; ++h) {
        double s = 0.0, q = 0.0;
        for (int x = t; x < BATCH*LSEQ; x += 256) {
            float v = g_w[((x >> 10)*NH + h)*LSEQ + (x & 1023)];
            s += v; q += (double)v * v;
        }
        ss[t] = s; sq[t] = q;
        __syncthreads();
        for (int o = 128; o; o >>= 1) {
            if (t < o) { ss[t] += ss[t+o]; sq[t] += sq[t+o]; }
            __syncthreads();
        }
        if (t == 0) {
            double n   = (double)BATCH * LSEQ;
            double m   = ss[0] / n;
            double var = sq[0] / n - m*m;
            double inv = rsqrt(var + 1e-5);
            float  a   = (float)(inv * (double)g2[h]);
            g_a2[h] = a;
            g_b2[h] = b2[h] - (float)m * a;
        }
        __syncthreads();
    }
}

// =================== K7: gate + length-masked softmax over L =============
__global__ void __launch_bounds__(1024) k7_gate(const float* __restrict__ Wp,
                                                const float* __restrict__ bp,
                                                float* __restrict__ w_out) {
    __shared__ float red[1024];
    int b = blockIdx.x, l = threadIdx.x;
    float z = bp[0] - bp[1];
    #pragma unroll
    for (int h = 0; h < NH; ++h) {
        float wv = g_a2[h]*g_w[(b*NH + h)*LSEQ + l] + g_b2[h];
        z += (Wp[h] - Wp[NH + h]) * wv;
    }
    float p0 = 1.f / (1.f + __expf(-z));
    bool valid = (g_valid[b*LSEQ + l] != 0);
    float val = valid ? p0 : -CUDART_INF_F;

    red[l] = val;
    __syncthreads();
    for (int o = 512; o; o >>= 1) {
        if (l < o) red[l] = fmaxf(red[l], red[l+o]);
        __syncthreads();
    }
    float mx = red[0];
    __syncthreads();
    float e = valid ? __expf(val - mx) : 0.f;
    red[l] = e;
    __syncthreads();
    for (int o = 512; o; o >>= 1) {
        if (l < o) red[l] += red[l+o];
        __syncthreads();
    }
    w_out[b*LSEQ + l] = e / red[0];
}

// ============================= launcher ==================================
extern "C" void kernel_launch(void* const* d_in, const int* in_sizes, int n_in,
                              void* d_out, int out_size) {
    const float* Q   = (const float*)d_in[0];
    const float* K   = (const float*)d_in[1];
    const float* V   = (const float*)d_in[2];
    const void*  pad = d_in[3];
    const void*  bx  = d_in[4];
    const float* g1  = (const float*)d_in[5];
    const float* b1  = (const float*)d_in[6];
    const float* g2  = (const float*)d_in[7];
    const float* b2  = (const float*)d_in[8];
    const float* Wp  = (const float*)d_in[9];
    const float* bp  = (const float*)d_in[10];

    float* co    = (float*)d_out;                  // (B,H,L,L)
    float* w_out = co + CO_ELEMS;                  // (B,L,1)
    float* vh    = w_out + W_ELEMS;                // (B,H,L,DH)

    static int smem_set = 0;
    const int K2_SMEM = 4*128*SJ*2 + 2*128*4;      // 140288 B
    const int K4_SMEM = 16*1024*4 + 1024;          // 66560 B
    if (!smem_set) {
        cudaFuncSetAttribute(k2_scores, cudaFuncAttributeMaxDynamicSharedMemorySize, K2_SMEM);
        cudaFuncSetAttribute(k4_softmax, cudaFuncAttributeMaxDynamicSharedMemorySize, K4_SMEM);
        smem_set = 1;
    }

    k0_setup<<<1, 256>>>((const unsigned int*)pad, (const unsigned char*)bx);
    k1_vh<<<BATCH*LSEQ, 192>>>(V, vh);
    k2_scores<<<dim3(8, 8, BHN), 256, K2_SMEM>>>(Q, K, co);
    k3_bn1<<<1, 32>>>(g1, b1);
    k4_softmax<<<BHN*64, 512, K4_SMEM>>>(co);
    k6_bn2<<<1, 256>>>(g2, b2);
    k7_gate<<<BATCH, 1024>>>(Wp, bp, w_out);
}